// round 1
// baseline (speedup 1.0000x reference)
#include <cuda_runtime.h>
#include <math.h>

typedef unsigned long long ull;
#define FULLMASK 0xffffffffu

// ---------------- device scratch (no allocations allowed) ----------------
__device__ float g_part1[4096];
__device__ float g_part2[256];

// ---------------- math helpers (match reference f32 expression order) -----
static __device__ __forceinline__ float sigf(float x) { return 1.0f / (1.0f + expf(-x)); }

static __device__ __forceinline__ float softplusf(float x) {
    // jax.nn.softplus: max(x,0) + log1p(exp(-|x|))
    return fmaxf(x, 0.0f) + log1pf(expf(-fabsf(x)));
}

static __device__ __forceinline__ float focalf(float x, float z) {
    float ce   = fmaxf(x, 0.0f) - x * z + log1pf(expf(-fabsf(x)));
    float prob = sigf(x);
    float pt   = prob * z + (1.0f - prob) * (1.0f - z);
    float at   = 0.25f * z + 0.75f * (1.0f - z);
    float om   = 1.0f - pt;
    return at * om * om * ce;
}

// Monotone float->uint mapping: smaller float => smaller uint (total order).
static __device__ __forceinline__ unsigned ford(float f) {
    unsigned u = __float_as_uint(f);
    return (u & 0x80000000u) ? ~u : (u | 0x80000000u);
}

// IoU of the predicted box at `cell` vs gt xyxy — used in both the candidate
// scan and the best_iou recompute so values agree bitwise.
static __device__ __forceinline__ float iou_cell(
    const float* __restrict__ predb, int HW, int Wd, float s, int cell,
    float gtx1, float gty1, float gtx2, float gty2, float garea)
{
    int   x  = cell % Wd, y = cell / Wd;
    float gx = (float)x, gy = (float)y;
    float q1 = __ldg(predb + HW + cell);
    float q2 = __ldg(predb + 2 * HW + cell);
    float q3 = __ldg(predb + 3 * HW + cell);
    float q4 = __ldg(predb + 4 * HW + cell);
    float pcx = (sigf(q1) + gx) * s;
    float pcy = (sigf(q2) + gy) * s;
    float pw  = expf(fminf(fmaxf(q3, -5.0f), 5.0f)) * s;
    float ph  = expf(fminf(fmaxf(q4, -5.0f), 5.0f)) * s;
    float px1 = pcx - pw * 0.5f, py1 = pcy - ph * 0.5f;
    float px2 = pcx + pw * 0.5f, py2 = pcy + ph * 0.5f;
    float iw    = fmaxf(fminf(px2, gtx2) - fmaxf(px1, gtx1), 0.0f);
    float ih    = fmaxf(fminf(py2, gty2) - fmaxf(py1, gty1), 0.0f);
    float inter = iw * ih;
    float pa    = (px2 - px1) * (py2 - py1);
    return inter / (pa + garea - inter + 1e-7f);
}

// ---------------- kernel 1: dense obj focal loss with z = 0 ----------------
__global__ void k_objbase(const float* __restrict__ p0,
                          const float* __restrict__ p1,
                          const float* __restrict__ p2)
{
    const long long N0 = 64LL * 25600, N1 = 64LL * 6400, N2 = 64LL * 1600;
    const long long total = N0 + N1 + N2;
    float acc = 0.0f;
    for (long long i = (long long)blockIdx.x * blockDim.x + threadIdx.x;
         i < total; i += (long long)gridDim.x * blockDim.x) {
        const float* p; long long b, c; float invHW; int HW;
        if (i < N0)            { HW = 25600; b = i / 25600;        c = i % 25600;        p = p0; invHW = 1.0f / 25600.0f; }
        else if (i < N0 + N1)  { long long j = i - N0;      HW = 6400; b = j / 6400; c = j % 6400; p = p1; invHW = 1.0f / 6400.0f; }
        else                   { long long j = i - N0 - N1; HW = 1600; b = j / 1600; c = j % 1600; p = p2; invHW = 1.0f / 1600.0f; }
        float x = __ldg(p + b * 7 * HW + c);  // channel 0
        acc += focalf(x, 0.0f) * invHW;
    }
    __shared__ float red[256];
    red[threadIdx.x] = acc;
    __syncthreads();
    for (int st = 128; st > 0; st >>= 1) {
        if (threadIdx.x < st) red[threadIdx.x] += red[threadIdx.x + st];
        __syncthreads();
    }
    if (threadIdx.x == 0) g_part1[blockIdx.x] = red[0];
}

// ---------------- kernel 2: assignment + positive-cell losses --------------
struct Sm {
    int   e_cell[400];
    float e_obj[400], e_b0[400], e_b1[400], e_b2[400], e_b3[400], e_f0[400], e_f1[400];
    int   r_idx[400];
    int   r_np[40];
    float r_biou[40], r_cxg[40], r_cyg[40], r_twt[40], r_tht[40], r_ft0[40], r_ft1[40];
    float red[256];
    int   nE;
    short table[25600];
};

__global__ void k_assign(const float* __restrict__ p0,
                         const float* __restrict__ p1,
                         const float* __restrict__ p2,
                         const float* __restrict__ tgt)
{
    extern __shared__ char smraw[];
    Sm& sm = *reinterpret_cast<Sm*>(smraw);

    int blk = blockIdx.x;
    int lvl = blk % 3, b = blk / 3;
    const float* pred; int Wd, HW; float s;
    if (lvl == 0)      { pred = p0; Wd = 160; HW = 25600; s = (float)(8.0  / 1280.0); }
    else if (lvl == 1) { pred = p1; Wd = 80;  HW = 6400;  s = (float)(16.0 / 1280.0); }
    else               { pred = p2; Wd = 40;  HW = 1600;  s = (float)(32.0 / 1280.0); }
    float invHW = 1.0f / (float)HW;
    const float* predb = pred + (size_t)b * 7 * HW;
    const float* tb    = tgt + (size_t)b * 40 * 7;

    int tid = threadIdx.x, lane = tid & 31, warp = tid >> 5;

    for (int i = tid; i < HW; i += 256) sm.table[i] = -1;
    if (tid < 40) sm.r_np[tid] = 0;
    if (tid == 0) sm.nE = 0;
    __syncthreads();

    // ---- per-warp GT processing (selection is GT-independent) ----
    for (int g = warp; g < 40; g += 8) {
        const float* T = tb + g * 7;
        float cls = T[0], cx = T[1], cy = T[2], w = T[3], h = T[4];
        float size = fmaxf(w, h) * 1280.0f;
        bool smask = (lvl == 0) ? (size < 128.0f)
                   : (lvl == 1) ? (size >= 48.0f && size < 288.0f)
                                : (size >= 128.0f);
        if (!(cls == 0.0f && smask)) continue;  // invalid GT is a provable no-op

        float cxg = cx / s, cyg = cy / s;
        float gtx1 = cx - w * 0.5f, gty1 = cy - h * 0.5f;
        float gtx2 = cx + w * 0.5f, gty2 = cy + h * 0.5f;
        float bxlo = gtx1 / s, bxhi = gtx2 / s, bylo = gty1 / s, byhi = gty2 / s;
        float garea = (gtx2 - gtx1) * (gty2 - gty1);

        // conservative hull of in_center ∪ in_box
        int x0 = max(0, (int)floorf(fminf(cxg - 2.5f, bxlo)));
        int x1 = min(Wd - 1, (int)ceilf(fmaxf(cxg + 2.5f, bxhi)));
        int y0 = max(0, (int)floorf(fminf(cyg - 2.5f, bylo)));
        int y1 = min(Wd - 1, (int)ceilf(fmaxf(cyg + 2.5f, byhi)));
        int nx = x1 - x0 + 1;
        int tot = nx * (y1 - y0 + 1);

        ull a[10];
        #pragma unroll
        for (int j = 0; j < 10; ++j) a[j] = ~0ull;
        int cnt = 0; float isum = 0.0f;

        for (int i = lane; i < tot; i += 32) {
            int x = x0 + i % nx, y = y0 + i / nx;
            float gx = (float)x, gy = (float)y;
            bool inc = (fabsf(gx - cxg) < 2.5f) & (fabsf(gy - cyg) < 2.5f);
            bool inb = (gx >= bxlo) & (gx < bxhi) & (gy >= bylo) & (gy < byhi);
            if (!(inc | inb)) continue;
            int cell = y * Wd + x;
            float iou = iou_cell(predb, HW, Wd, s, cell, gtx1, gty1, gtx2, gty2, garea);
            float q0  = __ldg(predb + cell);
            float cost = softplusf(-q0) - 3.0f * logf(iou + 1e-7f);
            cnt++; isum += iou;
            ull key = ((ull)ford(cost) << 32) | (unsigned)cell;
            if (key < a[9]) {                 // keep per-lane sorted top-10
                a[9] = key;
                #pragma unroll
                for (int j = 8; j >= 0; --j) {
                    ull lo = a[j] < a[j + 1] ? a[j] : a[j + 1];
                    ull hi = a[j] < a[j + 1] ? a[j + 1] : a[j];
                    a[j] = lo; a[j + 1] = hi;
                }
            }
        }
        #pragma unroll
        for (int o = 16; o; o >>= 1) {
            cnt  += __shfl_xor_sync(FULLMASK, cnt, o);
            isum += __shfl_xor_sync(FULLMASK, isum, o);
        }
        // extract global 10 smallest keys (ascending cost, idx tie-break == jax top_k)
        #pragma unroll
        for (int t = 0; t < 10; ++t) {
            ull m = a[0];
            #pragma unroll
            for (int o = 16; o; o >>= 1) {
                ull u = __shfl_xor_sync(FULLMASK, m, o);
                m = u < m ? u : m;
            }
            if (lane == 0)
                sm.r_idx[g * 10 + t] = (m == ~0ull) ? -1 : (int)(unsigned)(m & 0xffffffffu);
            if (a[0] == m && m != ~0ull) {    // unique owner pops its head
                #pragma unroll
                for (int j = 0; j < 9; ++j) a[j] = a[j + 1];
                a[9] = ~0ull;
            }
        }
        if (lane == 0 && cnt > 0) {
            int bc = sm.r_idx[g * 10];
            float biou = iou_cell(predb, HW, Wd, s, bc, gtx1, gty1, gtx2, gty2, garea);
            int hi = cnt < 10 ? cnt : 10;
            int np = (int)floorf(isum);
            np = np < 1 ? 1 : np;
            np = np > hi ? hi : np;
            sm.r_np[g]   = np;
            sm.r_biou[g] = biou;
            sm.r_cxg[g]  = cxg;  sm.r_cyg[g] = cyg;
            sm.r_twt[g]  = logf(w / s + 1e-7f);
            sm.r_tht[g]  = logf(h / s + 1e-7f);
            sm.r_ft0[g]  = T[5]; sm.r_ft1[g] = T[6];
        }
    }
    __syncthreads();

    // ---- sequential apply in GT order (preserves scan overwrite semantics) ----
    if (warp == 0) {
        for (int g = 0; g < 40; ++g) {
            int np = sm.r_np[g];
            if (lane < np) {
                int cell = sm.r_idx[g * 10 + lane];
                int slot = sm.table[cell];
                if (slot < 0) {
                    slot = atomicAdd(&sm.nE, 1);
                    sm.table[cell] = (short)slot;
                    sm.e_cell[slot] = cell;
                    sm.e_obj[slot]  = 0.0f;
                }
                sm.e_obj[slot] = fmaxf(sm.e_obj[slot], sm.r_biou[g]);
                float gxi = (float)(cell % Wd), gyi = (float)(cell / Wd);
                sm.e_b0[slot] = sm.r_cxg[g] - gxi;
                sm.e_b1[slot] = sm.r_cyg[g] - gyi;
                sm.e_b2[slot] = sm.r_twt[g];
                sm.e_b3[slot] = sm.r_tht[g];
                sm.e_f0[slot] = sm.r_ft0[g];
                sm.e_f1[slot] = sm.r_ft1[g];
            }
            __syncwarp();
        }
    }
    __syncthreads();

    // ---- losses over positive cells ----
    int nE = sm.nE;
    float npos = fmaxf((float)nE, 1.0f);
    float objc = 0.0f, boxs = 0.0f, fts = 0.0f;
    for (int e = tid; e < nE; e += 256) {
        int cell = sm.e_cell[e];
        float q0 = predb[cell];
        float q1 = predb[HW + cell],     q2 = predb[2 * HW + cell];
        float q3 = predb[3 * HW + cell], q4 = predb[4 * HW + cell];
        float q5 = predb[5 * HW + cell], q6 = predb[6 * HW + cell];

        float z = sm.e_obj[e];
        objc += focalf(q0, z) - focalf(q0, 0.0f);

        float gx = (float)(cell % Wd), gy = (float)(cell / Wd);
        float pcx = (sigf(q1) + gx) * s;
        float pcy = (sigf(q2) + gy) * s;
        float pw  = expf(fminf(fmaxf(q3, -5.0f), 5.0f)) * s;
        float ph  = expf(fminf(fmaxf(q4, -5.0f), 5.0f)) * s;
        float tcx = (sm.e_b0[e] + gx) * s;
        float tcy = (sm.e_b1[e] + gy) * s;
        float tw  = expf(sm.e_b2[e]) * s;
        float th  = expf(sm.e_b3[e]) * s;

        float px1 = pcx - pw * 0.5f, py1 = pcy - ph * 0.5f;
        float px2 = pcx + pw * 0.5f, py2 = pcy + ph * 0.5f;
        float tx1 = tcx - tw * 0.5f, ty1 = tcy - th * 0.5f;
        float tx2 = tcx + tw * 0.5f, ty2 = tcy + th * 0.5f;
        float iw    = fmaxf(fminf(px2, tx2) - fmaxf(px1, tx1), 0.0f);
        float ih    = fmaxf(fminf(py2, ty2) - fmaxf(py1, ty1), 0.0f);
        float inter = iw * ih;
        float uni   = pw * ph + tw * th - inter + 1e-7f;
        float iou   = inter / uni;
        float rho2  = (pcx - tcx) * (pcx - tcx) + (pcy - tcy) * (pcy - tcy);
        float cw = fmaxf(px2, tx2) - fminf(px1, tx1);
        float ch = fmaxf(py2, ty2) - fminf(py1, ty1);
        float c2 = cw * cw + ch * ch + 1e-7f;
        float dv = atanf(tw / (th + 1e-7f)) - atanf(pw / (ph + 1e-7f));
        float v  = 0.40528473456935108577f * dv * dv;  // 4/pi^2
        float alpha = v / (1.0f - iou + v + 1e-7f);
        float ciou  = iou - rho2 / c2 - alpha * v;
        boxs += 1.0f - ciou;

        float pf0 = sigf(q5), pf1 = sigf(q6);
        float d0 = fabsf(pf0 - sm.e_f0[e]);
        float d1 = fabsf(pf1 - sm.e_f1[e]);
        fts += (d0 < 1.0f ? 0.5f * d0 * d0 : d0 - 0.5f)
             + (d1 < 1.0f ? 0.5f * d1 * d1 : d1 - 0.5f);
    }

    // deterministic block reduction of the three sums
    sm.red[tid] = objc; __syncthreads();
    for (int st = 128; st > 0; st >>= 1) { if (tid < st) sm.red[tid] += sm.red[tid + st]; __syncthreads(); }
    float tobj = sm.red[0]; __syncthreads();
    sm.red[tid] = boxs; __syncthreads();
    for (int st = 128; st > 0; st >>= 1) { if (tid < st) sm.red[tid] += sm.red[tid + st]; __syncthreads(); }
    float tbox = sm.red[0]; __syncthreads();
    sm.red[tid] = fts; __syncthreads();
    for (int st = 128; st > 0; st >>= 1) { if (tid < st) sm.red[tid] += sm.red[tid + st]; __syncthreads(); }
    float tft = sm.red[0];

    if (tid == 0)
        g_part2[blk] = tobj * invHW + 5.0f * tbox / npos + 1.0f * tft / npos;
}

// ---------------- kernel 3: deterministic final reduction ------------------
__global__ void k_final(float* __restrict__ out, int nb1)
{
    __shared__ float red[256];
    float acc = 0.0f;
    for (int i = threadIdx.x; i < nb1; i += 256) acc += g_part1[i];
    for (int i = threadIdx.x; i < 192; i += 256) acc += g_part2[i];
    red[threadIdx.x] = acc;
    __syncthreads();
    for (int st = 128; st > 0; st >>= 1) {
        if (threadIdx.x < st) red[threadIdx.x] += red[threadIdx.x + st];
        __syncthreads();
    }
    if (threadIdx.x == 0) out[0] = red[0] / 64.0f;
}

// ---------------- host ----------------
extern "C" void kernel_launch(void* const* d_in, const int* in_sizes, int n_in,
                              void* d_out, int out_size)
{
    const float *p0 = nullptr, *p1 = nullptr, *p2 = nullptr, *tg = nullptr;
    for (int i = 0; i < n_in; ++i) {
        int sz = in_sizes[i];
        if      (sz == 64 * 7 * 160 * 160) p0 = (const float*)d_in[i];
        else if (sz == 64 * 7 * 80 * 80)   p1 = (const float*)d_in[i];
        else if (sz == 64 * 7 * 40 * 40)   p2 = (const float*)d_in[i];
        else if (sz == 64 * 40 * 7)        tg = (const float*)d_in[i];
    }

    cudaFuncSetAttribute(k_assign, cudaFuncAttributeMaxDynamicSharedMemorySize,
                         (int)sizeof(Sm));

    const int nb1 = 2048;
    k_objbase<<<nb1, 256>>>(p0, p1, p2);
    k_assign<<<192, 256, sizeof(Sm)>>>(p0, p1, p2, tg);
    k_final<<<1, 256>>>((float*)d_out, nb1);
}

// round 3
// speedup vs baseline: 1.8520x; 1.8520x over previous
#include <cuda_runtime.h>
#include <math.h>

typedef unsigned long long ull;
#define FULLMASK 0xffffffffu

#define NSEL_BLOCKS   960          // 7680 warps = 64 b * 3 lvl * 40 gt
#define NDENSE_BLOCKS 1088
#define NTOT_BLOCKS   (NSEL_BLOCKS + NDENSE_BLOCKS)

// ---------------- device scratch (no allocations allowed) ----------------
struct SelR {
    int   idx[10];
    int   np;
    float biou, cxg, cyg, twt, tht, f0, f1;
    int   pad;
};
__device__ SelR  g_sel[7680];
__device__ float g_part1[NDENSE_BLOCKS];
__device__ float g_part2[192];

// ---------------- fast math helpers ----------------
static __device__ __forceinline__ float fsig(float x) {
    return __fdividef(1.0f, 1.0f + __expf(-x));
}
static __device__ __forceinline__ float fsoftplus(float x) {
    return fmaxf(x, 0.0f) + __logf(1.0f + __expf(-fabsf(x)));
}
// focal(x, 0) = 0.75 * sigmoid(x)^2 * softplus(x)
static __device__ __forceinline__ float ffocal0(float x) {
    float ce   = fmaxf(x, 0.0f) + __logf(1.0f + __expf(-fabsf(x)));
    float prob = fsig(x);
    return 0.75f * prob * prob * ce;
}
static __device__ __forceinline__ float ffocal(float x, float z) {
    float ce   = fmaxf(x, 0.0f) - x * z + __logf(1.0f + __expf(-fabsf(x)));
    float prob = fsig(x);
    float pt   = prob * z + (1.0f - prob) * (1.0f - z);
    float at   = 0.25f * z + 0.75f * (1.0f - z);
    float om   = 1.0f - pt;
    return at * om * om * ce;
}

// Monotone float->uint mapping: smaller float => smaller uint (total order).
static __device__ __forceinline__ unsigned ford(float f) {
    unsigned u = __float_as_uint(f);
    return (u & 0x80000000u) ? ~u : (u | 0x80000000u);
}

// IoU of predicted box at `cell` vs gt xyxy.
static __device__ __forceinline__ float iou_cell(
    const float* __restrict__ predb, int HW, int Wd, float s, int cell,
    float gtx1, float gty1, float gtx2, float gty2, float garea)
{
    int   x  = cell % Wd, y = cell / Wd;
    float gx = (float)x, gy = (float)y;
    float q1 = __ldg(predb + HW + cell);
    float q2 = __ldg(predb + 2 * HW + cell);
    float q3 = __ldg(predb + 3 * HW + cell);
    float q4 = __ldg(predb + 4 * HW + cell);
    float pcx = (fsig(q1) + gx) * s;
    float pcy = (fsig(q2) + gy) * s;
    float pw  = __expf(fminf(fmaxf(q3, -5.0f), 5.0f)) * s;
    float ph  = __expf(fminf(fmaxf(q4, -5.0f), 5.0f)) * s;
    float px1 = pcx - pw * 0.5f, py1 = pcy - ph * 0.5f;
    float px2 = pcx + pw * 0.5f, py2 = pcy + ph * 0.5f;
    float iw    = fmaxf(fminf(px2, gtx2) - fmaxf(px1, gtx1), 0.0f);
    float ih    = fmaxf(fminf(py2, gty2) - fmaxf(py1, gty1), 0.0f);
    float inter = iw * ih;
    float pa    = (px2 - px1) * (py2 - py1);
    return __fdividef(inter, pa + garea - inter + 1e-7f);
}

// ---------------- kernel 1: fused selection (warp-per-GT) + dense focal ----
__global__ void k_main(const float* __restrict__ p0,
                       const float* __restrict__ p1,
                       const float* __restrict__ p2,
                       const float* __restrict__ tgt)
{
    if (blockIdx.x >= NSEL_BLOCKS) {
        int bi = blockIdx.x - NSEL_BLOCKS;
        const int STRD = NDENSE_BLOCKS * 256;
        float acc = 0.0f;
        for (int i = bi * 256 + threadIdx.x; i < 64 * 25600; i += STRD) {
            float x = __ldg(p0 + i + (i / 25600) * 6 * 25600);
            acc += ffocal0(x) * (1.0f / 25600.0f);
        }
        for (int i = bi * 256 + threadIdx.x; i < 64 * 6400; i += STRD) {
            float x = __ldg(p1 + i + (i / 6400) * 6 * 6400);
            acc += ffocal0(x) * (1.0f / 6400.0f);
        }
        for (int i = bi * 256 + threadIdx.x; i < 64 * 1600; i += STRD) {
            float x = __ldg(p2 + i + (i / 1600) * 6 * 1600);
            acc += ffocal0(x) * (1.0f / 1600.0f);
        }
        __shared__ float red[256];
        red[threadIdx.x] = acc;
        __syncthreads();
        for (int st = 128; st > 0; st >>= 1) {
            if (threadIdx.x < st) red[threadIdx.x] += red[threadIdx.x + st];
            __syncthreads();
        }
        if (threadIdx.x == 0) g_part1[bi] = red[0];
        return;
    }

    // ---------- selection: one warp per (b, lvl, gt) ----------
    int lane = threadIdx.x & 31;
    int gw   = blockIdx.x * 8 + (threadIdx.x >> 5);   // 0..7679
    int g    = gw % 40;
    int r    = gw / 40;                                // 0..191
    int b    = r & 63;
    int lvl  = r >> 6;

    const float* pred; int Wd, HW; float s;
    if (lvl == 0)      { pred = p0; Wd = 160; HW = 25600; s = (float)(8.0  / 1280.0); }
    else if (lvl == 1) { pred = p1; Wd = 80;  HW = 6400;  s = (float)(16.0 / 1280.0); }
    else               { pred = p2; Wd = 40;  HW = 1600;  s = (float)(32.0 / 1280.0); }
    const float* predb = pred + (size_t)b * 7 * HW;
    const float* T     = tgt + (size_t)(b * 40 + g) * 7;

    float cls = __ldg(T + 0), cx = __ldg(T + 1), cy = __ldg(T + 2);
    float w   = __ldg(T + 3), h  = __ldg(T + 4);
    float size = fmaxf(w, h) * 1280.0f;
    bool smask = (lvl == 0) ? (size < 128.0f)
               : (lvl == 1) ? (size >= 48.0f && size < 288.0f)
                            : (size >= 128.0f);
    if (!(cls == 0.0f && smask)) {                    // invalid GT: no-op
        if (lane == 0) g_sel[gw].np = 0;
        return;
    }

    float cxg = cx / s, cyg = cy / s;
    float gtx1 = cx - w * 0.5f, gty1 = cy - h * 0.5f;
    float gtx2 = cx + w * 0.5f, gty2 = cy + h * 0.5f;
    float bxlo = gtx1 / s, bxhi = gtx2 / s, bylo = gty1 / s, byhi = gty2 / s;
    float garea = (gtx2 - gtx1) * (gty2 - gty1);

    int x0 = max(0, (int)floorf(fminf(cxg - 2.5f, bxlo)));
    int x1 = min(Wd - 1, (int)ceilf(fmaxf(cxg + 2.5f, bxhi)));
    int y0 = max(0, (int)floorf(fminf(cyg - 2.5f, bylo)));
    int y1 = min(Wd - 1, (int)ceilf(fmaxf(cyg + 2.5f, byhi)));
    int nx  = x1 - x0 + 1;
    int tot = nx * (y1 - y0 + 1);

    ull a[10];
    #pragma unroll
    for (int j = 0; j < 10; ++j) a[j] = ~0ull;
    int cnt = 0; float isum = 0.0f;

    for (int i = lane; i < tot; i += 32) {
        int x = x0 + i % nx, y = y0 + i / nx;
        float gx = (float)x, gy = (float)y;
        bool inc = (fabsf(gx - cxg) < 2.5f) & (fabsf(gy - cyg) < 2.5f);
        bool inb = (gx >= bxlo) & (gx < bxhi) & (gy >= bylo) & (gy < byhi);
        if (!(inc | inb)) continue;
        int cell = y * Wd + x;
        float iou  = iou_cell(predb, HW, Wd, s, cell, gtx1, gty1, gtx2, gty2, garea);
        float q0   = __ldg(predb + cell);
        float cost = fsoftplus(-q0) - 3.0f * __logf(iou + 1e-7f);
        cnt++; isum += iou;
        ull key = ((ull)ford(cost) << 32) | (unsigned)cell;
        if (key < a[9]) {
            a[9] = key;
            #pragma unroll
            for (int j = 8; j >= 0; --j) {
                ull lo = a[j] < a[j + 1] ? a[j] : a[j + 1];
                ull hi = a[j] < a[j + 1] ? a[j + 1] : a[j];
                a[j] = lo; a[j + 1] = hi;
            }
        }
    }
    #pragma unroll
    for (int o = 16; o; o >>= 1) {
        cnt  += __shfl_xor_sync(FULLMASK, cnt, o);
        isum += __shfl_xor_sync(FULLMASK, isum, o);
    }

    int bc0 = -1;
    #pragma unroll
    for (int t = 0; t < 10; ++t) {
        ull m = a[0];
        #pragma unroll
        for (int o = 16; o; o >>= 1) {
            ull u = __shfl_xor_sync(FULLMASK, m, o);
            m = u < m ? u : m;
        }
        int cellv = (m == ~0ull) ? -1 : (int)(unsigned)(m & 0xffffffffu);
        if (t == 0) bc0 = cellv;
        if (lane == 0) g_sel[gw].idx[t] = cellv;
        if (a[0] == m && m != ~0ull) {
            #pragma unroll
            for (int j = 0; j < 9; ++j) a[j] = a[j + 1];
            a[9] = ~0ull;
        }
    }
    if (lane == 0) {
        if (cnt > 0) {
            float biou = iou_cell(predb, HW, Wd, s, bc0, gtx1, gty1, gtx2, gty2, garea);
            int hi = cnt < 10 ? cnt : 10;
            int np = (int)floorf(isum);
            np = np < 1 ? 1 : np;
            np = np > hi ? hi : np;
            SelR& sr = g_sel[gw];
            sr.np = np;   sr.biou = biou;
            sr.cxg = cxg; sr.cyg = cyg;
            sr.twt = __logf(w / s + 1e-7f);
            sr.tht = __logf(h / s + 1e-7f);
            sr.f0  = __ldg(T + 5); sr.f1 = __ldg(T + 6);
        } else {
            g_sel[gw].np = 0;
        }
    }
}

// ---------------- kernel 2: sequential apply + positive-cell losses --------
struct Sm2 {
    int   e_cell[400];
    float e_obj[400], e_b0[400], e_b1[400], e_b2[400], e_b3[400], e_f0[400], e_f1[400];
    SelR  sel[40];
    float red[256];
    int   nE;
    short table[25600];
};

__global__ void k_apply(const float* __restrict__ p0,
                        const float* __restrict__ p1,
                        const float* __restrict__ p2)
{
    extern __shared__ char smraw[];
    Sm2& sm = *reinterpret_cast<Sm2*>(smraw);

    int blk = blockIdx.x;           // = (lvl*64 + b)
    int b   = blk & 63, lvl = blk >> 6;
    const float* pred; int Wd, HW; float s;
    if (lvl == 0)      { pred = p0; Wd = 160; HW = 25600; s = (float)(8.0  / 1280.0); }
    else if (lvl == 1) { pred = p1; Wd = 80;  HW = 6400;  s = (float)(16.0 / 1280.0); }
    else               { pred = p2; Wd = 40;  HW = 1600;  s = (float)(32.0 / 1280.0); }
    float invHW = 1.0f / (float)HW;
    const float* predb = pred + (size_t)b * 7 * HW;

    int tid = threadIdx.x, lane = tid & 31, warp = tid >> 5;

    {
        const int* src = (const int*)&g_sel[blk * 40];
        int*       dst = (int*)sm.sel;
        for (int i = tid; i < 40 * (int)(sizeof(SelR) / 4); i += 256) dst[i] = src[i];
    }
    if (tid == 0) sm.nE = 0;
    __syncthreads();

    // BUGFIX: strided loop (blockDim is 256; `if (tid < 400)` left GTs 26..39
    // uncleared -> garbage slots -> shared OOB writes -> illegal access)
    for (int i = tid; i < 400; i += 256) {
        int g = i / 10, k = i % 10;
        if (k < sm.sel[g].np) sm.table[sm.sel[g].idx[k]] = -1;
    }
    __syncthreads();

    if (warp == 0) {
        for (int g = 0; g < 40; ++g) {
            const SelR& sr = sm.sel[g];
            if (lane < sr.np) {
                int cell = sr.idx[lane];
                int slot = sm.table[cell];
                if (slot < 0) {
                    slot = atomicAdd(&sm.nE, 1);
                    sm.table[cell] = (short)slot;
                    sm.e_cell[slot] = cell;
                    sm.e_obj[slot]  = 0.0f;
                }
                sm.e_obj[slot] = fmaxf(sm.e_obj[slot], sr.biou);
                float gxi = (float)(cell % Wd), gyi = (float)(cell / Wd);
                sm.e_b0[slot] = sr.cxg - gxi;
                sm.e_b1[slot] = sr.cyg - gyi;
                sm.e_b2[slot] = sr.twt;
                sm.e_b3[slot] = sr.tht;
                sm.e_f0[slot] = sr.f0;
                sm.e_f1[slot] = sr.f1;
            }
            __syncwarp();
        }
    }
    __syncthreads();

    int nE = sm.nE;
    float npos = fmaxf((float)nE, 1.0f);
    float objc = 0.0f, boxs = 0.0f, fts = 0.0f;
    for (int e = tid; e < nE; e += 256) {
        int cell = sm.e_cell[e];
        float q0 = __ldg(predb + cell);
        float q1 = __ldg(predb + HW + cell);
        float q2 = __ldg(predb + 2 * HW + cell);
        float q3 = __ldg(predb + 3 * HW + cell);
        float q4 = __ldg(predb + 4 * HW + cell);
        float q5 = __ldg(predb + 5 * HW + cell);
        float q6 = __ldg(predb + 6 * HW + cell);

        float z = sm.e_obj[e];
        objc += ffocal(q0, z) - ffocal0(q0);

        float gx = (float)(cell % Wd), gy = (float)(cell / Wd);
        float pcx = (fsig(q1) + gx) * s;
        float pcy = (fsig(q2) + gy) * s;
        float pw  = __expf(fminf(fmaxf(q3, -5.0f), 5.0f)) * s;
        float ph  = __expf(fminf(fmaxf(q4, -5.0f), 5.0f)) * s;
        float tcx = (sm.e_b0[e] + gx) * s;
        float tcy = (sm.e_b1[e] + gy) * s;
        float tw  = __expf(sm.e_b2[e]) * s;
        float th  = __expf(sm.e_b3[e]) * s;

        float px1 = pcx - pw * 0.5f, py1 = pcy - ph * 0.5f;
        float px2 = pcx + pw * 0.5f, py2 = pcy + ph * 0.5f;
        float tx1 = tcx - tw * 0.5f, ty1 = tcy - th * 0.5f;
        float tx2 = tcx + tw * 0.5f, ty2 = tcy + th * 0.5f;
        float iw    = fmaxf(fminf(px2, tx2) - fmaxf(px1, tx1), 0.0f);
        float ih    = fmaxf(fminf(py2, ty2) - fmaxf(py1, ty1), 0.0f);
        float inter = iw * ih;
        float uni   = pw * ph + tw * th - inter + 1e-7f;
        float iou   = __fdividef(inter, uni);
        float rho2  = (pcx - tcx) * (pcx - tcx) + (pcy - tcy) * (pcy - tcy);
        float cw = fmaxf(px2, tx2) - fminf(px1, tx1);
        float ch = fmaxf(py2, ty2) - fminf(py1, ty1);
        float c2 = cw * cw + ch * ch + 1e-7f;
        float dv = atanf(__fdividef(tw, th + 1e-7f)) - atanf(__fdividef(pw, ph + 1e-7f));
        float v  = 0.40528473456935108577f * dv * dv;          // 4/pi^2
        float alpha = __fdividef(v, 1.0f - iou + v + 1e-7f);
        float ciou  = iou - __fdividef(rho2, c2) - alpha * v;
        boxs += 1.0f - ciou;

        float pf0 = fsig(q5), pf1 = fsig(q6);
        float d0 = fabsf(pf0 - sm.e_f0[e]);
        float d1 = fabsf(pf1 - sm.e_f1[e]);
        fts += (d0 < 1.0f ? 0.5f * d0 * d0 : d0 - 0.5f)
             + (d1 < 1.0f ? 0.5f * d1 * d1 : d1 - 0.5f);
    }

    sm.red[tid] = objc; __syncthreads();
    for (int st = 128; st > 0; st >>= 1) { if (tid < st) sm.red[tid] += sm.red[tid + st]; __syncthreads(); }
    float tobj = sm.red[0]; __syncthreads();
    sm.red[tid] = boxs; __syncthreads();
    for (int st = 128; st > 0; st >>= 1) { if (tid < st) sm.red[tid] += sm.red[tid + st]; __syncthreads(); }
    float tbox = sm.red[0]; __syncthreads();
    sm.red[tid] = fts; __syncthreads();
    for (int st = 128; st > 0; st >>= 1) { if (tid < st) sm.red[tid] += sm.red[tid + st]; __syncthreads(); }
    float tft = sm.red[0];

    if (tid == 0)
        g_part2[blk] = tobj * invHW + 5.0f * tbox / npos + 1.0f * tft / npos;
}

// ---------------- kernel 3: deterministic final reduction ------------------
__global__ void k_final(float* __restrict__ out)
{
    __shared__ float red[256];
    float acc = 0.0f;
    for (int i = threadIdx.x; i < NDENSE_BLOCKS; i += 256) acc += g_part1[i];
    for (int i = threadIdx.x; i < 192; i += 256) acc += g_part2[i];
    red[threadIdx.x] = acc;
    __syncthreads();
    for (int st = 128; st > 0; st >>= 1) {
        if (threadIdx.x < st) red[threadIdx.x] += red[threadIdx.x + st];
        __syncthreads();
    }
    if (threadIdx.x == 0) out[0] = red[0] / 64.0f;
}

// ---------------- host ----------------
extern "C" void kernel_launch(void* const* d_in, const int* in_sizes, int n_in,
                              void* d_out, int out_size)
{
    const float *p0 = nullptr, *p1 = nullptr, *p2 = nullptr, *tg = nullptr;
    for (int i = 0; i < n_in; ++i) {
        int sz = in_sizes[i];
        if      (sz == 64 * 7 * 160 * 160) p0 = (const float*)d_in[i];
        else if (sz == 64 * 7 * 80 * 80)   p1 = (const float*)d_in[i];
        else if (sz == 64 * 7 * 40 * 40)   p2 = (const float*)d_in[i];
        else if (sz == 64 * 40 * 7)        tg = (const float*)d_in[i];
    }

    cudaFuncSetAttribute(k_apply, cudaFuncAttributeMaxDynamicSharedMemorySize,
                         (int)sizeof(Sm2));

    k_main<<<NTOT_BLOCKS, 256>>>(p0, p1, p2, tg);
    k_apply<<<192, 256, sizeof(Sm2)>>>(p0, p1, p2);
    k_final<<<1, 256>>>((float*)d_out);
}

// round 4
// speedup vs baseline: 2.0305x; 1.0964x over previous
#include <cuda_runtime.h>
#include <math.h>

typedef unsigned long long ull;
#define FULLMASK 0xffffffffu

#define NSEL_GROUPS 192
#define NDENSE      252
#define GRID_ALL    (NSEL_GROUPS + NDENSE)   // 444 = 12 groups of 37 (16 sel + 21 dense)

// ---------------- device scratch ----------------
__device__ float    g_part[GRID_ALL];
__device__ unsigned g_count = 0;

struct SelR {
    int   idx[10];
    int   np;
    float biou, cxg, cyg, twt, tht, f0, f1;
};

struct SmG {
    int      table[25600];                       // owner-g, then slot
    int      e_cell[400];
    unsigned e_obj[400];
    float    e_b0[400], e_b1[400], e_b2[400], e_b3[400], e_f0[400], e_f1[400];
    SelR     sel[40];
    float    red[32];
    int      wcnt[32], wbase[32];
    int      nE;
    int      last;
};

// ---------------- fast math helpers ----------------
static __device__ __forceinline__ float fsig(float x) {
    return __fdividef(1.0f, 1.0f + __expf(-x));
}
static __device__ __forceinline__ float fsoftplus(float x) {
    return fmaxf(x, 0.0f) + __logf(1.0f + __expf(-fabsf(x)));
}
static __device__ __forceinline__ float ffocal0(float x) {
    float ce   = fmaxf(x, 0.0f) + __logf(1.0f + __expf(-fabsf(x)));
    float prob = fsig(x);
    return 0.75f * prob * prob * ce;
}
static __device__ __forceinline__ float ffocal(float x, float z) {
    float ce   = fmaxf(x, 0.0f) - x * z + __logf(1.0f + __expf(-fabsf(x)));
    float prob = fsig(x);
    float pt   = prob * z + (1.0f - prob) * (1.0f - z);
    float at   = 0.25f * z + 0.75f * (1.0f - z);
    float om   = 1.0f - pt;
    return at * om * om * ce;
}
static __device__ __forceinline__ unsigned ford(float f) {
    unsigned u = __float_as_uint(f);
    return (u & 0x80000000u) ? ~u : (u | 0x80000000u);
}

static __device__ __forceinline__ float iou_cell(
    const float* __restrict__ predb, int HW, int Wd, float s, int cell,
    float gtx1, float gty1, float gtx2, float gty2, float garea)
{
    int   x  = cell % Wd, y = cell / Wd;
    float gx = (float)x, gy = (float)y;
    float q1 = __ldg(predb + HW + cell);
    float q2 = __ldg(predb + 2 * HW + cell);
    float q3 = __ldg(predb + 3 * HW + cell);
    float q4 = __ldg(predb + 4 * HW + cell);
    float pcx = (fsig(q1) + gx) * s;
    float pcy = (fsig(q2) + gy) * s;
    float pw  = __expf(fminf(fmaxf(q3, -5.0f), 5.0f)) * s;
    float ph  = __expf(fminf(fmaxf(q4, -5.0f), 5.0f)) * s;
    float px1 = pcx - pw * 0.5f, py1 = pcy - ph * 0.5f;
    float px2 = pcx + pw * 0.5f, py2 = pcy + ph * 0.5f;
    float iw    = fmaxf(fminf(px2, gtx2) - fmaxf(px1, gtx1), 0.0f);
    float ih    = fmaxf(fminf(py2, gty2) - fmaxf(py1, gty1), 0.0f);
    float inter = iw * ih;
    float pa    = (px2 - px1) * (py2 - py1);
    return __fdividef(inter, pa + garea - inter + 1e-7f);
}

// block reduce over 32 warps; valid result in warp 0 (all lanes). Deterministic.
static __device__ __forceinline__ float blk_reduce(float v, float* red, int tid) {
    #pragma unroll
    for (int o = 16; o; o >>= 1) v += __shfl_xor_sync(FULLMASK, v, o);
    if ((tid & 31) == 0) red[tid >> 5] = v;
    __syncthreads();
    float r = 0.0f;
    if (tid < 32) {
        r = red[tid];
        #pragma unroll
        for (int o = 16; o; o >>= 1) r += __shfl_xor_sync(FULLMASK, r, o);
    }
    __syncthreads();
    return r;
}

// ---------------- the single kernel ----------------
__global__ void __launch_bounds__(1024, 1)
k_all(const float* __restrict__ p0, const float* __restrict__ p1,
      const float* __restrict__ p2, const float* __restrict__ tgt,
      float* __restrict__ out)
{
    extern __shared__ char smraw[];
    SmG& sm = *reinterpret_cast<SmG*>(smraw);
    int tid = threadIdx.x;
    int grp = blockIdx.x / 37, rem = blockIdx.x % 37;
    float part = 0.0f;

    if (rem >= 16) {
        // ================= dense obj focal base (z = 0) =================
        int di = grp * 21 + (rem - 16);           // 0..251
        const int STRD = NDENSE * 1024;
        float acc = 0.0f;
        for (int i = di * 1024 + tid; i < 64 * 25600; i += STRD) {
            float x = __ldg(p0 + i + (i / 25600) * 6 * 25600);
            acc += ffocal0(x) * (1.0f / 25600.0f);
        }
        for (int i = di * 1024 + tid; i < 64 * 6400; i += STRD) {
            float x = __ldg(p1 + i + (i / 6400) * 6 * 6400);
            acc += ffocal0(x) * (1.0f / 6400.0f);
        }
        for (int i = di * 1024 + tid; i < 64 * 1600; i += STRD) {
            float x = __ldg(p2 + i + (i / 1600) * 6 * 1600);
            acc += ffocal0(x) * (1.0f / 1600.0f);
        }
        part = blk_reduce(acc, sm.red, tid);
    } else {
        // ================= group block: one (b, lvl) =================
        int blk = grp * 16 + rem;                 // 0..191 = lvl*64 + b
        int b = blk & 63, lvl = blk >> 6;
        const float* pred; int Wd, HW; float s;
        if (lvl == 0)      { pred = p0; Wd = 160; HW = 25600; s = (float)(8.0  / 1280.0); }
        else if (lvl == 1) { pred = p1; Wd = 80;  HW = 6400;  s = (float)(16.0 / 1280.0); }
        else               { pred = p2; Wd = 40;  HW = 1600;  s = (float)(32.0 / 1280.0); }
        float invHW = 1.0f / (float)HW;
        const float* predb = pred + (size_t)b * 7 * HW;
        const float* tb    = tgt + (size_t)b * 40 * 7;

        int warp = tid >> 5, lane = tid & 31;

        // ---- selection: warp w handles GTs g = w, w+32 ----
        for (int g = warp; g < 40; g += 32) {
            const float* T = tb + g * 7;
            float cls = __ldg(T + 0), cx = __ldg(T + 1), cy = __ldg(T + 2);
            float w   = __ldg(T + 3), h  = __ldg(T + 4);
            float size = fmaxf(w, h) * 1280.0f;
            bool smask = (lvl == 0) ? (size < 128.0f)
                       : (lvl == 1) ? (size >= 48.0f && size < 288.0f)
                                    : (size >= 128.0f);
            if (!(cls == 0.0f && smask)) {        // invalid GT: provable no-op
                if (lane == 0) sm.sel[g].np = 0;
                continue;
            }
            float cxg = cx / s, cyg = cy / s;
            float gtx1 = cx - w * 0.5f, gty1 = cy - h * 0.5f;
            float gtx2 = cx + w * 0.5f, gty2 = cy + h * 0.5f;
            float bxlo = gtx1 / s, bxhi = gtx2 / s, bylo = gty1 / s, byhi = gty2 / s;
            float garea = (gtx2 - gtx1) * (gty2 - gty1);

            int x0 = max(0, (int)floorf(fminf(cxg - 2.5f, bxlo)));
            int x1 = min(Wd - 1, (int)ceilf(fmaxf(cxg + 2.5f, bxhi)));
            int y0 = max(0, (int)floorf(fminf(cyg - 2.5f, bylo)));
            int y1 = min(Wd - 1, (int)ceilf(fmaxf(cyg + 2.5f, byhi)));
            int nx  = x1 - x0 + 1;
            int tot = nx * (y1 - y0 + 1);

            ull a[10];
            #pragma unroll
            for (int j = 0; j < 10; ++j) a[j] = ~0ull;
            int cnt = 0; float isum = 0.0f;

            for (int i = lane; i < tot; i += 32) {
                int x = x0 + i % nx, y = y0 + i / nx;
                float gx = (float)x, gy = (float)y;
                bool inc = (fabsf(gx - cxg) < 2.5f) & (fabsf(gy - cyg) < 2.5f);
                bool inb = (gx >= bxlo) & (gx < bxhi) & (gy >= bylo) & (gy < byhi);
                if (!(inc | inb)) continue;
                int cell = y * Wd + x;
                float iou  = iou_cell(predb, HW, Wd, s, cell, gtx1, gty1, gtx2, gty2, garea);
                float q0   = __ldg(predb + cell);
                float cost = fsoftplus(-q0) - 3.0f * __logf(iou + 1e-7f);
                cnt++; isum += iou;
                ull key = ((ull)ford(cost) << 32) | (unsigned)cell;
                if (key < a[9]) {
                    a[9] = key;
                    #pragma unroll
                    for (int j = 8; j >= 0; --j) {
                        ull lo = a[j] < a[j + 1] ? a[j] : a[j + 1];
                        ull hi = a[j] < a[j + 1] ? a[j + 1] : a[j];
                        a[j] = lo; a[j + 1] = hi;
                    }
                }
            }
            #pragma unroll
            for (int o = 16; o; o >>= 1) {
                cnt  += __shfl_xor_sync(FULLMASK, cnt, o);
                isum += __shfl_xor_sync(FULLMASK, isum, o);
            }

            int bc0 = -1;
            #pragma unroll
            for (int t = 0; t < 10; ++t) {
                ull m = a[0];
                #pragma unroll
                for (int o = 16; o; o >>= 1) {
                    ull u = __shfl_xor_sync(FULLMASK, m, o);
                    m = u < m ? u : m;
                }
                int cellv = (m == ~0ull) ? -1 : (int)(unsigned)(m & 0xffffffffu);
                if (t == 0) bc0 = cellv;
                if (lane == 0) sm.sel[g].idx[t] = cellv;
                if (a[0] == m && m != ~0ull) {
                    #pragma unroll
                    for (int j = 0; j < 9; ++j) a[j] = a[j + 1];
                    a[9] = ~0ull;
                }
            }
            if (lane == 0) {
                if (cnt > 0) {
                    float biou = iou_cell(predb, HW, Wd, s, bc0, gtx1, gty1, gtx2, gty2, garea);
                    int hi = cnt < 10 ? cnt : 10;
                    int np = (int)floorf(isum);
                    np = np < 1 ? 1 : np;
                    np = np > hi ? hi : np;
                    SelR& sr = sm.sel[g];
                    sr.np = np;   sr.biou = biou;
                    sr.cxg = cxg; sr.cyg = cyg;
                    sr.twt = __logf(w / s + 1e-7f);
                    sr.tht = __logf(h / s + 1e-7f);
                    sr.f0  = __ldg(T + 5); sr.f1 = __ldg(T + 6);
                } else {
                    sm.sel[g].np = 0;
                }
            }
        }
        __syncthreads();

        // ---- parallel apply: owner = max g (last-writer-wins), obj = max biou ----
        int  gp   = tid / 10, kp = tid % 10;
        bool act  = (tid < 400) && (kp < sm.sel[gp].np);
        int  cell = act ? sm.sel[gp].idx[kp] : 0;

        if (act) sm.table[cell] = -1;              // clear only touched cells
        __syncthreads();
        if (act) atomicMax(&sm.table[cell], gp);   // ownership
        __syncthreads();
        bool own = act && (sm.table[cell] == gp);

        // deterministic slot assignment: ballot + warp-count prefix scan
        unsigned bal  = __ballot_sync(FULLMASK, own);
        int      wpre = __popc(bal & ((1u << lane) - 1));
        if (lane == 0) sm.wcnt[warp] = __popc(bal);
        __syncthreads();
        if (tid == 0) {
            int ssum = 0;
            #pragma unroll
            for (int w2 = 0; w2 < 32; ++w2) { sm.wbase[w2] = ssum; ssum += sm.wcnt[w2]; }
            sm.nE = ssum;
        }
        __syncthreads();

        int slot = -1;
        if (own) {
            slot = sm.wbase[warp] + wpre;
            const SelR& sr = sm.sel[gp];
            float gxi = (float)(cell % Wd), gyi = (float)(cell / Wd);
            sm.e_cell[slot] = cell;
            sm.e_obj[slot]  = 0u;
            sm.e_b0[slot] = sr.cxg - gxi;
            sm.e_b1[slot] = sr.cyg - gyi;
            sm.e_b2[slot] = sr.twt;
            sm.e_b3[slot] = sr.tht;
            sm.e_f0[slot] = sr.f0;
            sm.e_f1[slot] = sr.f1;
        }
        __syncthreads();
        if (own) sm.table[cell] = slot;            // publish slot
        __syncthreads();
        if (act)                                   // max biou over all selecting GTs
            atomicMax(&sm.e_obj[sm.table[cell]], __float_as_uint(sm.sel[gp].biou));
        __syncthreads();

        // ---- losses over positive cells (1 entry / thread) ----
        int nE = sm.nE;
        float npos = fmaxf((float)nE, 1.0f);
        float objc = 0.0f, boxs = 0.0f, fts = 0.0f;
        if (tid < nE) {
            int cl = sm.e_cell[tid];
            float q0 = __ldg(predb + cl);
            float q1 = __ldg(predb + HW + cl);
            float q2 = __ldg(predb + 2 * HW + cl);
            float q3 = __ldg(predb + 3 * HW + cl);
            float q4 = __ldg(predb + 4 * HW + cl);
            float q5 = __ldg(predb + 5 * HW + cl);
            float q6 = __ldg(predb + 6 * HW + cl);

            float z = __uint_as_float(sm.e_obj[tid]);
            objc = ffocal(q0, z) - ffocal0(q0);

            float gx = (float)(cl % Wd), gy = (float)(cl / Wd);
            float pcx = (fsig(q1) + gx) * s;
            float pcy = (fsig(q2) + gy) * s;
            float pw  = __expf(fminf(fmaxf(q3, -5.0f), 5.0f)) * s;
            float ph  = __expf(fminf(fmaxf(q4, -5.0f), 5.0f)) * s;
            float tcx = (sm.e_b0[tid] + gx) * s;
            float tcy = (sm.e_b1[tid] + gy) * s;
            float tw  = __expf(sm.e_b2[tid]) * s;
            float th  = __expf(sm.e_b3[tid]) * s;

            float px1 = pcx - pw * 0.5f, py1 = pcy - ph * 0.5f;
            float px2 = pcx + pw * 0.5f, py2 = pcy + ph * 0.5f;
            float tx1 = tcx - tw * 0.5f, ty1 = tcy - th * 0.5f;
            float tx2 = tcx + tw * 0.5f, ty2 = tcy + th * 0.5f;
            float iw    = fmaxf(fminf(px2, tx2) - fmaxf(px1, tx1), 0.0f);
            float ih    = fmaxf(fminf(py2, ty2) - fmaxf(py1, ty1), 0.0f);
            float inter = iw * ih;
            float uni   = pw * ph + tw * th - inter + 1e-7f;
            float iou   = __fdividef(inter, uni);
            float rho2  = (pcx - tcx) * (pcx - tcx) + (pcy - tcy) * (pcy - tcy);
            float cw = fmaxf(px2, tx2) - fminf(px1, tx1);
            float ch = fmaxf(py2, ty2) - fminf(py1, ty1);
            float c2 = cw * cw + ch * ch + 1e-7f;
            float dv = atanf(__fdividef(tw, th + 1e-7f)) - atanf(__fdividef(pw, ph + 1e-7f));
            float v  = 0.40528473456935108577f * dv * dv;      // 4/pi^2
            float alpha = __fdividef(v, 1.0f - iou + v + 1e-7f);
            float ciou  = iou - __fdividef(rho2, c2) - alpha * v;
            boxs = 1.0f - ciou;

            float pf0 = fsig(q5), pf1 = fsig(q6);
            float d0 = fabsf(pf0 - sm.e_f0[tid]);
            float d1 = fabsf(pf1 - sm.e_f1[tid]);
            fts = (d0 < 1.0f ? 0.5f * d0 * d0 : d0 - 0.5f)
                + (d1 < 1.0f ? 0.5f * d1 * d1 : d1 - 0.5f);
        }

        float tobj = blk_reduce(objc, sm.red, tid);
        float tbox = blk_reduce(boxs, sm.red, tid);
        float tft  = blk_reduce(fts,  sm.red, tid);
        part = tobj * invHW + 5.0f * tbox / npos + 1.0f * tft / npos;
    }

    // ---- arrival counter; last block does the deterministic final sum ----
    if (tid == 0) {
        g_part[blockIdx.x] = part;
        __threadfence();
        unsigned t = atomicAdd(&g_count, 1u);
        sm.last = (t == GRID_ALL - 1) ? 1 : 0;
    }
    __syncthreads();
    if (sm.last) {
        __threadfence();
        float acc = 0.0f;
        for (int i = tid; i < GRID_ALL; i += 1024) acc += g_part[i];
        float tot = blk_reduce(acc, sm.red, tid);
        if (tid == 0) {
            out[0] = tot / 64.0f;
            g_count = 0;                 // reset for next graph replay
        }
    }
}

// ---------------- host ----------------
extern "C" void kernel_launch(void* const* d_in, const int* in_sizes, int n_in,
                              void* d_out, int out_size)
{
    const float *p0 = nullptr, *p1 = nullptr, *p2 = nullptr, *tg = nullptr;
    for (int i = 0; i < n_in; ++i) {
        int sz = in_sizes[i];
        if      (sz == 64 * 7 * 160 * 160) p0 = (const float*)d_in[i];
        else if (sz == 64 * 7 * 80 * 80)   p1 = (const float*)d_in[i];
        else if (sz == 64 * 7 * 40 * 40)   p2 = (const float*)d_in[i];
        else if (sz == 64 * 40 * 7)        tg = (const float*)d_in[i];
    }

    cudaFuncSetAttribute(k_all, cudaFuncAttributeMaxDynamicSharedMemorySize,
                         (int)sizeof(SmG));

    k_all<<<GRID_ALL, 1024, sizeof(SmG)>>>(p0, p1, p2, tg, (float*)d_out);
}